// round 6
// baseline (speedup 1.0000x reference)
#include <cuda_runtime.h>
#include <cuda_bf16.h>
#include <cstdint>

// ---------------- problem dims ----------------
#define BB 64
#define TT 512
#define II 128
#define NN 2048
#define NTILES 16
#define KSP 9                // 8 recurrent k-slices of 256 + 1 input slice
#define KSLICE 256
#define GRID (NTILES * KSP)  // 144 CTAs, co-resident (1 per SM)
#define NTHREADS 256

// ---------------- smem layout (bytes) ----------------
#define A_STRIDE 528
#define B_STRIDE 144
#define A_HI 0
#define A_LO (128 * A_STRIDE)
#define B_HI (2 * 128 * A_STRIDE)
#define B_LO (B_HI + 256 * B_STRIDE)
#define SMEM_DYN (B_LO + 256 * B_STRIDE) // 208896

// ---------------- device globals ----------------
__device__ float g_h[2][NN * BB];                 // hidden state, [n][b]
__device__ float g_partial[KSP][NN * BB];         // split-K partials, [n][b]
__device__ __nv_bfloat16 g_rhi[NN * BB];          // relu(h) hi, [n][b] (single buffer)
__device__ __nv_bfloat16 g_rlo[NN * BB];
__device__ __nv_bfloat16 g_xhi[TT * II * BB];     // x hi, [t][i][b]
__device__ __nv_bfloat16 g_xlo[TT * II * BB];
// sync counters, all memset to 0 each launch:
// [0:16) P[nt], [16:32) C[nt], [32:40) Rdy[s], [40:48) Bdone[s], [48] arrive
__device__ unsigned int g_sync[64];

#define P_CNT  (&g_sync[0])
#define C_CNT  (&g_sync[16])
#define RDY    (&g_sync[32])
#define BDONE  (&g_sync[40])
#define ARRIVE (&g_sync[48])

// ---------------- helpers ----------------
__device__ __forceinline__ uint32_t smem_u32(const void* p) {
    uint32_t a;
    asm("{ .reg .u64 t; cvta.to.shared.u64 t, %1; cvt.u32.u64 %0, t; }" : "=r"(a) : "l"(p));
    return a;
}
__device__ __forceinline__ void ldsm4(uint32_t* r, uint32_t addr) {
    asm volatile("ldmatrix.sync.aligned.m8n8.x4.shared.b16 {%0,%1,%2,%3}, [%4];"
                 : "=r"(r[0]), "=r"(r[1]), "=r"(r[2]), "=r"(r[3]) : "r"(addr));
}
__device__ __forceinline__ void ldsm4t(uint32_t* r, uint32_t addr) {
    asm volatile("ldmatrix.sync.aligned.m8n8.x4.trans.shared.b16 {%0,%1,%2,%3}, [%4];"
                 : "=r"(r[0]), "=r"(r[1]), "=r"(r[2]), "=r"(r[3]) : "r"(addr));
}
__device__ __forceinline__ void mma16816(float* d, const uint32_t* a, const uint32_t* b) {
    asm volatile(
        "mma.sync.aligned.m16n8k16.row.col.f32.bf16.bf16.f32 "
        "{%0,%1,%2,%3}, {%4,%5,%6,%7}, {%8,%9}, {%0,%1,%2,%3};"
        : "+f"(d[0]), "+f"(d[1]), "+f"(d[2]), "+f"(d[3])
        : "r"(a[0]), "r"(a[1]), "r"(a[2]), "r"(a[3]), "r"(b[0]), "r"(b[1]));
}

// release-increment (call from tid 0 AFTER __syncthreads)
__device__ __forceinline__ void sig_add(unsigned int* p, unsigned int v) {
    asm volatile("red.release.gpu.global.add.u32 [%0], %1;" :: "l"(p), "r"(v) : "memory");
}
__device__ __forceinline__ unsigned int ld_acq(const unsigned int* p) {
    unsigned int v;
    asm volatile("ld.acquire.gpu.global.u32 %0, [%1];" : "=r"(v) : "l"(p) : "memory");
    return v;
}
// tid-0 poll; caller must __syncthreads() after
__device__ __forceinline__ void poll_ge(const unsigned int* p, unsigned int tgt) {
    while (ld_acq(p) < tgt) { __nanosleep(32); }
}

__device__ __forceinline__ void grid_barrier_once(unsigned int target) {
    __threadfence();
    __syncthreads();
    if (threadIdx.x == 0) {
        atomicAdd(ARRIVE, 1u);
        while (*(volatile unsigned int*)ARRIVE < target) { __nanosleep(64); }
        __threadfence();
    }
    __syncthreads();
}

__device__ __forceinline__ void load_frags(uint32_t aBase, uint32_t bBase, int kk,
                                           uint32_t* ahi, uint32_t* alo,
                                           uint32_t (*bhi)[2], uint32_t (*blo)[2]) {
    const uint32_t aA = aBase + (uint32_t)kk * 32;
    ldsm4(ahi, aA);
    ldsm4(alo, aA + (A_LO - A_HI));
    const uint32_t bA = bBase + (uint32_t)kk * 16 * B_STRIDE;
#pragma unroll
    for (int p = 0; p < 4; ++p) {
        ldsm4t(&bhi[2 * p][0], bA + p * 32);
        ldsm4t(&blo[2 * p][0], bA + p * 32 + (B_LO - B_HI));
    }
}

// ---------------- persistent RNN kernel ----------------
__global__ void __launch_bounds__(NTHREADS, 1) rnn_persistent(
    const float* __restrict__ x,      // [B,T,I]
    const float* __restrict__ h0,     // [B,N]
    const float* __restrict__ Wrec,   // [N,N]
    const float* __restrict__ Winp,   // [N,I]
    const float* __restrict__ tonic,  // [N]
    const int*   __restrict__ mask,   // [N,N]
    const int*   __restrict__ sgn,    // [N,N]
    float* __restrict__ out)          // [B,T,N]
{
    extern __shared__ __align__(16) char sm[];
    const uint32_t smb = smem_u32(sm);
    __shared__ float sm_out[64][17];

    const int cta = blockIdx.x;
    const int nt  = cta % NTILES;
    const int ks  = cta / NTILES;
    const int n0  = nt * 128;
    const int k0  = ks * KSLICE;
    const int tid = threadIdx.x;
    const int wid = tid >> 5;
    const int lane = tid & 31;
    const bool inp = (ks == KSP - 1);
    const int KSTEPS = inp ? (II / 16) : (KSLICE / 16);

    // reducer ownership: contiguous rows
    const int Rrows = (cta < 32) ? 15 : 14;
    const int nbase = cta * 14 + min(cta, 32);
    const int T1 = nbase >> 7;                      // tiles touched
    const int T2 = (nbase + Rrows - 1) >> 7;
    const int s1 = nbase >> 8;                      // r-slices touched
    const int s2 = (nbase + Rrows - 1) >> 8;
    const int rows1 = (s1 == s2) ? Rrows : (256 * (s1 + 1) - nbase);
    const int rows2 = Rrows - rows1;

    // ======== prologue (once per launch) ========
    for (int idx = tid; idx < 128 * 256; idx += NTHREADS) {
        int m = idx >> 8, c = idx & 255;
        int n = n0 + m;
        float v = 0.0f;
        if (!inp) {
            int k = k0 + c;
            float w = Wrec[n * NN + k];
            int ms = mask[n * NN + k] * sgn[n * NN + k];
            v = fmaxf(w, 0.0f) * (float)ms;
        } else if (c < II) {
            v = Winp[n * II + c];
        }
        __nv_bfloat16 hi = __float2bfloat16(v);
        __nv_bfloat16 lo = __float2bfloat16(v - __bfloat162float(hi));
        *(__nv_bfloat16*)(sm + A_HI + m * A_STRIDE + c * 2) = hi;
        *(__nv_bfloat16*)(sm + A_LO + m * A_STRIDE + c * 2) = lo;
    }
    {
        int gid = cta * NTHREADS + tid;
        if (gid < (NN * BB) / 4) {
            int base = gid * 4;
            int n = base >> 6, b0 = base & 63;
            float hv[4];
#pragma unroll
            for (int u = 0; u < 4; ++u) hv[u] = h0[(size_t)(b0 + u) * NN + n];
            *(float4*)&g_h[0][base] = make_float4(hv[0], hv[1], hv[2], hv[3]);
            __nv_bfloat16 hi4[4], lo4[4];
#pragma unroll
            for (int u = 0; u < 4; ++u) {
                float r = fmaxf(hv[u], 0.0f);
                hi4[u] = __float2bfloat16(r);
                lo4[u] = __float2bfloat16(r - __bfloat162float(hi4[u]));
            }
            *(uint2*)&g_rhi[base] = *(uint2*)hi4;
            *(uint2*)&g_rlo[base] = *(uint2*)lo4;
        }
    }
    for (int gid = cta * NTHREADS + tid; gid < (TT * II * BB) / 4; gid += GRID * NTHREADS) {
        int base = gid * 4;
        int b0 = base & 63;
        int i  = (base >> 6) & (II - 1);
        int t  = base >> 13;
        __nv_bfloat16 hi4[4], lo4[4];
#pragma unroll
        for (int u = 0; u < 4; ++u) {
            float v = __ldg(&x[((size_t)(b0 + u) * TT + t) * II + i]);
            hi4[u] = __float2bfloat16(v);
            lo4[u] = __float2bfloat16(v - __bfloat162float(hi4[u]));
        }
        *(uint2*)&g_xhi[base] = *(uint2*)hi4;
        *(uint2*)&g_xlo[base] = *(uint2*)lo4;
    }
    // nRed[nt]: reducers touching my tile nt
    int nRed = 0;
    for (int c = 0; c < GRID; ++c) {
        int nb = c * 14 + min(c, 32);
        int re = nb + ((c < 32) ? 15 : 14);
        if (nb < 128 * (nt + 1) && re > 128 * nt) nRed++;
    }

    grid_barrier_once(GRID);

    const uint32_t aBase = smb + A_HI + (uint32_t)(wid * 16 + (lane & 15)) * A_STRIDE
                           + (uint32_t)(lane >> 4) * 16;
    const uint32_t bBase = smb + B_HI
                           + (uint32_t)((lane & 7) + ((lane >> 3) & 1) * 8) * B_STRIDE
                           + (uint32_t)(lane >> 4) * 16;

    const float AC = 0.1f, OMA = 0.9f;

    for (int t = 0; t < TT; ++t) {
        const float* __restrict__ cur = g_h[t & 1];
        float* __restrict__ nxt = g_h[(t + 1) & 1];

        // ---- producer: wait r(t-1) ready for my slice ----
        if (!inp && t > 0) {
            if (tid == 0) poll_ge(RDY + ks, 256u * (unsigned)t);
            __syncthreads();
        }

        // ---- B-copy ----
        {
            const char* srcHi = inp ? (const char*)&g_xhi[(size_t)t * II * BB]
                                    : (const char*)&g_rhi[(size_t)k0 * BB];
            const char* srcLo = inp ? (const char*)&g_xlo[(size_t)t * II * BB]
                                    : (const char*)&g_rlo[(size_t)k0 * BB];
            const int rows = inp ? II : KSLICE;
            for (int idx = tid; idx < rows * 8; idx += NTHREADS) {
                int r = idx >> 3, c16 = (idx & 7) * 16;
                uint4 vh = __ldcg((const uint4*)(srcHi + r * 128 + c16));
                uint4 vl = __ldcg((const uint4*)(srcLo + r * 128 + c16));
                *(uint4*)(sm + B_HI + r * B_STRIDE + c16) = vh;
                *(uint4*)(sm + B_LO + r * B_STRIDE + c16) = vl;
            }
        }
        __syncthreads();
        if (tid == 0 && !inp) sig_add(BDONE + ks, 1u);   // r slice consumed

        // ---- MMA ----
        float acc[8][4];
#pragma unroll
        for (int j = 0; j < 8; ++j)
#pragma unroll
            for (int q = 0; q < 4; ++q) acc[j][q] = 0.0f;

        uint32_t ahi[2][4], alo[2][4], bhi[2][8][2], blo[2][8][2];
        load_frags(aBase, bBase, 0, ahi[0], alo[0], bhi[0], blo[0]);
#pragma unroll 2
        for (int kk = 0; kk < KSTEPS; ++kk) {
            const int cb = kk & 1;
            if (kk + 1 < KSTEPS)
                load_frags(aBase, bBase, kk + 1, ahi[cb ^ 1], alo[cb ^ 1],
                           bhi[cb ^ 1], blo[cb ^ 1]);
#pragma unroll
            for (int nb = 0; nb < 8; ++nb) {
                mma16816(acc[nb], ahi[cb], bhi[cb][nb]);
                mma16816(acc[nb], ahi[cb], blo[cb][nb]);
                mma16816(acc[nb], alo[cb], bhi[cb][nb]);
            }
        }

        // ---- wait partials(t-1) consumed, then store partials(t) ----
        if (t > 0) {
            if (tid == 0) poll_ge(C_CNT + nt, (unsigned)nRed * (unsigned)t);
            __syncthreads();
        }
        {
            float* dst = &g_partial[ks][0];
            const int gi = lane >> 2;
            const int ti = lane & 3;
            const int r0 = n0 + wid * 16 + gi;
#pragma unroll
            for (int nb = 0; nb < 8; ++nb) {
                int cb2 = nb * 8 + 2 * ti;
                __stcg((float2*)&dst[(size_t)r0 * BB + cb2],
                       make_float2(acc[nb][0], acc[nb][1]));
                __stcg((float2*)&dst[(size_t)(r0 + 8) * BB + cb2],
                       make_float2(acc[nb][2], acc[nb][3]));
            }
        }
        __syncthreads();
        if (tid == 0) sig_add(P_CNT + nt, 1u);

        // ---- reducer: wait partials ready + my r rows consumed ----
        if (tid == 0) {
            unsigned ptgt = 9u * (unsigned)(t + 1);
            poll_ge(P_CNT + T1, ptgt);
            if (T2 != T1) poll_ge(P_CNT + T2, ptgt);
            unsigned btgt = 16u * (unsigned)(t + 1);
            poll_ge(BDONE + s1, btgt);
            if (s2 != s1) poll_ge(BDONE + s2, btgt);
        }
        __syncthreads();

        // ---- reduce + update + relu + publish r ----
        if (tid < Rrows * 16) {
            int r = tid >> 4;
            int b0 = (tid & 15) * 4;
            int n = nbase + r;
            size_t off = (size_t)n * BB + b0;

            float4 s = make_float4(0.f, 0.f, 0.f, 0.f);
#pragma unroll
            for (int p = 0; p < KSP; ++p) {
                float4 q = __ldcg((const float4*)&g_partial[p][off]);
                s.x += q.x; s.y += q.y; s.z += q.z; s.w += q.w;
            }
            float tn = __ldg(&tonic[n]);
            float4 hv = __ldcg((const float4*)&cur[off]);
            float4 r4;
            r4.x = OMA * hv.x + AC * (s.x + tn);
            r4.y = OMA * hv.y + AC * (s.y + tn);
            r4.z = OMA * hv.z + AC * (s.z + tn);
            r4.w = OMA * hv.w + AC * (s.w + tn);
            __stcg((float4*)&nxt[off], r4);

            float rr[4] = {fmaxf(r4.x, 0.f), fmaxf(r4.y, 0.f),
                           fmaxf(r4.z, 0.f), fmaxf(r4.w, 0.f)};
            __nv_bfloat16 hi4[4], lo4[4];
#pragma unroll
            for (int u = 0; u < 4; ++u) {
                hi4[u] = __float2bfloat16(rr[u]);
                lo4[u] = __float2bfloat16(rr[u] - __bfloat162float(hi4[u]));
                sm_out[b0 + u][r] = rr[u];
            }
            *(uint2*)&g_rhi[off] = *(uint2*)hi4;
            *(uint2*)&g_rlo[off] = *(uint2*)lo4;
        }
        __syncthreads();
        if (tid == 0) {
            sig_add(C_CNT + T1, 1u);
            if (T2 != T1) sig_add(C_CNT + T2, 1u);
            sig_add(RDY + s1, (unsigned)rows1);
            if (s2 != s1) sig_add(RDY + s2, (unsigned)rows2);
        }

        // ---- out write (off critical path, overlaps other CTAs) ----
        for (int idx = tid; idx < Rrows * 64; idx += NTHREADS) {
            int b = idx / Rrows;
            int rr2 = idx - b * Rrows;
            out[((size_t)b * TT + t) * NN + nbase + rr2] = sm_out[b][rr2];
        }
    }
}

// ---------------- launch ----------------
extern "C" void kernel_launch(void* const* d_in, const int* in_sizes, int n_in,
                              void* d_out, int out_size) {
    const float* x     = (const float*)d_in[0];
    const float* h0    = (const float*)d_in[1];
    const float* Wrec  = (const float*)d_in[2];
    const float* Winp  = (const float*)d_in[3];
    const float* tonic = (const float*)d_in[4];
    const int*   mask  = (const int*)d_in[5];
    const int*   sgn   = (const int*)d_in[6];
    float* out = (float*)d_out;

    cudaFuncSetAttribute(rnn_persistent,
                         cudaFuncAttributeMaxDynamicSharedMemorySize, SMEM_DYN);

    void* pa = nullptr;
    cudaGetSymbolAddress(&pa, g_sync);
    cudaMemsetAsync(pa, 0, sizeof(unsigned int) * 64);

    rnn_persistent<<<GRID, NTHREADS, SMEM_DYN>>>(x, h0, Wrec, Winp, tonic,
                                                 mask, sgn, out);
}